// round 1
// baseline (speedup 1.0000x reference)
#include <cuda_runtime.h>
#include <cuda_bf16.h>
#include <math.h>

// ---------------------------------------------------------------------------
// Problem constants (shapes fixed by setup_inputs)
// ---------------------------------------------------------------------------
#define NBATCH   4
#define HDIM     128
#define WDIM     128
#define DM       768
#define NHEADS   12
#define DHEAD    64
#define DFF      2048
#define DC       768
#define WS       8
#define SHIFT    4
#define TOKENS   (NBATCH * HDIM * WDIM)          // 65536
#define NWIN     (NBATCH * NHEADS * 16 * 16)     // 12288 window-heads
#define EPSV     1e-6f

// ---------------------------------------------------------------------------
// Scratch (static device globals -- allocation-free rule)
// ---------------------------------------------------------------------------
__device__ float g_scale1[NBATCH * DM];
__device__ float g_scale2[NBATCH * DM];
__device__ float g_h   [(size_t)TOKENS * DM];         // rmsnormed activations
__device__ float g_qkv [(size_t)TOKENS * 3 * DM];     // qkv GEMM output
__device__ float g_qw  [(size_t)NWIN * 64 * 64];      // windowed q (post norm+rope)
__device__ float g_kw  [(size_t)NWIN * 64 * 64];
__device__ float g_vw  [(size_t)NWIN * 64 * 64];
__device__ float g_ow  [(size_t)NWIN * 64 * 64];      // attention out (windowed)
__device__ float g_oimg[(size_t)TOKENS * DM];         // unwindowed attention out
__device__ float g_x2  [(size_t)TOKENS * DM];         // x after first residual
__device__ float g_u   [(size_t)TOKENS * 2 * DFF];    // ff_up output
__device__ float g_act [(size_t)TOKENS * DFF];        // a * gelu(g)

// ---------------------------------------------------------------------------
// K0: ada scales  scale[n,d] = cond[n,:] . w[d,:] + 1
// ---------------------------------------------------------------------------
__global__ void ada_kernel(const float* __restrict__ cond,
                           const float* __restrict__ w1,
                           const float* __restrict__ w2)
{
    int gw   = (blockIdx.x * blockDim.x + threadIdx.x) >> 5;
    int lane = threadIdx.x & 31;
    if (gw >= 2 * NBATCH * DM) return;
    int which = gw / (NBATCH * DM);
    int rem   = gw % (NBATCH * DM);
    int n = rem / DM, d = rem % DM;
    const float* w  = which ? w2 : w1;
    const float* cr = cond + n * DC;
    const float* wr = w + (size_t)d * DC;
    float s = 0.f;
    for (int i = lane; i < DC; i += 32) s += cr[i] * wr[i];
    #pragma unroll
    for (int o = 16; o; o >>= 1) s += __shfl_xor_sync(0xffffffffu, s, o);
    if (lane == 0) (which ? g_scale2 : g_scale1)[rem] = s + 1.0f;
}

// ---------------------------------------------------------------------------
// K1: fused RMSNorm * ada-scale. One block (256 thr) per token, 3 elems/thr.
// ---------------------------------------------------------------------------
__global__ __launch_bounds__(256) void rmsnorm_kernel(const float* __restrict__ x,
                                                      const float* __restrict__ scale,
                                                      float* __restrict__ out)
{
    int t = blockIdx.x;
    int n = t >> 14;  // /16384
    const float* xr = x + (size_t)t * DM;
    float v[3]; float ss = 0.f;
    #pragma unroll
    for (int i = 0; i < 3; i++) { v[i] = xr[threadIdx.x + 256 * i]; ss += v[i] * v[i]; }
    __shared__ float red[8];
    #pragma unroll
    for (int o = 16; o; o >>= 1) ss += __shfl_xor_sync(0xffffffffu, ss, o);
    if ((threadIdx.x & 31) == 0) red[threadIdx.x >> 5] = ss;
    __syncthreads();
    if (threadIdx.x == 0) {
        float r = 0.f;
        #pragma unroll
        for (int i = 0; i < 8; i++) r += red[i];
        red[0] = r;
    }
    __syncthreads();
    float inv = rsqrtf(red[0] * (1.0f / DM) + EPSV);
    const float* sc = scale + (size_t)n * DM;
    float* orow = out + (size_t)t * DM;
    #pragma unroll
    for (int i = 0; i < 3; i++) {
        int c = threadIdx.x + 256 * i;
        orow[c] = v[i] * sc[c] * inv;
    }
}

// ---------------------------------------------------------------------------
// K2: SGEMM  C[m,n] = (D ? D[m,n] : 0) + sum_k A[m,k] * B[n,k]
// A row-major MxK, B row-major NxK (i.e. C = A @ B^T). 128x128x8 tile,
// 8x8 per thread, 256 threads.
// ---------------------------------------------------------------------------
__global__ __launch_bounds__(256) void sgemm_nt_kernel(const float* __restrict__ A,
                                                       const float* __restrict__ B,
                                                       const float* __restrict__ D,
                                                       float* __restrict__ C,
                                                       int M, int N, int K)
{
    __shared__ float As[8][128];
    __shared__ float Bs[8][128];

    int bm  = blockIdx.y * 128;
    int bn  = blockIdx.x * 128;
    int tid = threadIdx.x;

    int lr = tid >> 1;           // 0..127 row within tile
    int lk = (tid & 1) << 2;     // 0 or 4
    const float* Ab = A + (size_t)(bm + lr) * K + lk;
    const float* Bb = B + (size_t)(bn + lr) * K + lk;

    int tx = tid & 15;           // col group
    int ty = tid >> 4;           // row group

    float acc[8][8];
    #pragma unroll
    for (int i = 0; i < 8; i++)
        #pragma unroll
        for (int j = 0; j < 8; j++) acc[i][j] = 0.f;

    for (int k0 = 0; k0 < K; k0 += 8) {
        float4 av = *(const float4*)(Ab + k0);
        float4 bv = *(const float4*)(Bb + k0);
        __syncthreads();
        As[lk + 0][lr] = av.x; As[lk + 1][lr] = av.y;
        As[lk + 2][lr] = av.z; As[lk + 3][lr] = av.w;
        Bs[lk + 0][lr] = bv.x; Bs[lk + 1][lr] = bv.y;
        Bs[lk + 2][lr] = bv.z; Bs[lk + 3][lr] = bv.w;
        __syncthreads();
        #pragma unroll
        for (int kk = 0; kk < 8; kk++) {
            float a[8], b[8];
            *(float4*)(a + 0) = *(const float4*)&As[kk][ty * 8 + 0];
            *(float4*)(a + 4) = *(const float4*)&As[kk][ty * 8 + 4];
            *(float4*)(b + 0) = *(const float4*)&Bs[kk][tx * 8 + 0];
            *(float4*)(b + 4) = *(const float4*)&Bs[kk][tx * 8 + 4];
            #pragma unroll
            for (int i = 0; i < 8; i++)
                #pragma unroll
                for (int j = 0; j < 8; j++) acc[i][j] += a[i] * b[j];
        }
    }

    #pragma unroll
    for (int i = 0; i < 8; i++) {
        size_t row = (size_t)(bm + ty * 8 + i);
        float* crow = C + row * N + bn + tx * 8;
        #pragma unroll
        for (int j = 0; j < 8; j += 4) {
            float4 v = make_float4(acc[i][j], acc[i][j + 1], acc[i][j + 2], acc[i][j + 3]);
            if (D) {
                float4 dv = *(const float4*)(D + row * N + bn + tx * 8 + j);
                v.x += dv.x; v.y += dv.y; v.z += dv.z; v.w += dv.w;
            }
            *(float4*)(crow + j) = v;
        }
    }
}

// ---------------------------------------------------------------------------
// K3: per-head q/k L2-norm * sqrt(attn_scale), RoPE, shift-roll + windowing
// scatter of q,k,v. 12 warps per block (one per head), one block per token.
// ---------------------------------------------------------------------------
__global__ __launch_bounds__(384) void qk_transform_kernel(const float* __restrict__ pos,
                                                           const float* __restrict__ attn_scale,
                                                           const float* __restrict__ rope_freqs)
{
    int t = blockIdx.x;
    int h = threadIdx.x >> 5;
    int l = threadIdx.x & 31;
    int n = t >> 14;
    int y = (t >> 7) & 127;
    int x = t & 127;

    const float* base = g_qkv + (size_t)t * (3 * DM) + h * DHEAD;
    float q0 = base[l],            q1 = base[l + 32];
    float k0 = base[DM + l],       k1 = base[DM + l + 32];
    float v0 = base[2 * DM + l],   v1 = base[2 * DM + l + 32];

    float sq = q0 * q0 + q1 * q1;
    float sk = k0 * k0 + k1 * k1;
    #pragma unroll
    for (int o = 16; o; o >>= 1) {
        sq += __shfl_xor_sync(0xffffffffu, sq, o);
        sk += __shfl_xor_sync(0xffffffffu, sk, o);
    }
    float ssh = sqrtf(attn_scale[h]);
    float rq = ssh * rsqrtf(sq + EPSV);
    float rk = ssh * rsqrtf(sk + EPSV);
    q0 *= rq; q1 *= rq; k0 *= rk; k1 *= rk;

    // RoPE on elems 0..31 (pairs (e, e+16)); elems 32..63 pass through.
    float p0 = pos[(size_t)t * 2 + 0];
    float p1 = pos[(size_t)t * 2 + 1];
    int f = l & 15;
    float freq = rope_freqs[h * 8 + (f & 7)];
    float th = (f < 8 ? p0 : p1) * freq;
    float c = cosf(th), s = sinf(th);
    float qp = __shfl_xor_sync(0xffffffffu, q0, 16);
    float kp = __shfl_xor_sync(0xffffffffu, k0, 16);
    if (l < 16) { q0 = q0 * c - qp * s; k0 = k0 * c - kp * s; }
    else        { q0 = q0 * c + qp * s; k0 = k0 * c + kp * s; }

    // roll(+4,+4) then window
    int Y = (y + SHIFT) & 127, X = (x + SHIFT) & 127;
    int win  = ((n * NHEADS + h) * 16 + (Y >> 3)) * 16 + (X >> 3);
    int spos = (Y & 7) * 8 + (X & 7);
    size_t o = (size_t)win * 4096 + (size_t)spos * 64 + l;
    g_qw[o] = q0; g_qw[o + 32] = q1;
    g_kw[o] = k0; g_kw[o + 32] = k1;
    g_vw[o] = v0; g_vw[o + 32] = v1;
}

// ---------------------------------------------------------------------------
// K4: windowed attention. One block (64 threads) per window-head.
// 64x64x64 fp32 attention with shift mask. 48 KB smem exactly.
// ---------------------------------------------------------------------------
#define QT(e, r) qT[(e) * 64 + (((r) + (e)) & 63)]   // swizzled transpose store

__global__ __launch_bounds__(64) void attn_kernel()
{
    __shared__ float qT[64 * 64];
    __shared__ float ks[64][64];
    __shared__ float vs[64][64];

    int b   = blockIdx.x;
    int w   = b & 255;
    int wwi = w & 15, whi = (w >> 4) & 15;
    bool left = (wwi == 0), top = (whi == 0);

    const float* qb = g_qw + (size_t)b * 4096;
    const float* kb = g_kw + (size_t)b * 4096;
    const float* vb = g_vw + (size_t)b * 4096;
    int tid = threadIdx.x;

    // cooperative coalesced load (1024 float4 per tile)
    for (int i = tid; i < 1024; i += 64) {
        int r = i >> 4, c = (i & 15) << 2;
        float4 kv = *(const float4*)(kb + (i << 2));
        *(float4*)&ks[r][c] = kv;
        float4 vv = *(const float4*)(vb + (i << 2));
        *(float4*)&vs[r][c] = vv;
        float4 qv = *(const float4*)(qb + (i << 2));
        QT(c + 0, r) = qv.x; QT(c + 1, r) = qv.y;
        QT(c + 2, r) = qv.z; QT(c + 3, r) = qv.w;
    }
    __syncthreads();

    // scores: query = tid
    float sarr[64];
    #pragma unroll
    for (int k = 0; k < 64; k++) sarr[k] = 0.f;
    for (int e = 0; e < 64; e += 4) {
        float q0 = QT(e + 0, tid), q1 = QT(e + 1, tid);
        float q2 = QT(e + 2, tid), q3 = QT(e + 3, tid);
        #pragma unroll
        for (int k = 0; k < 64; k++) {
            float4 kv = *(const float4*)&ks[k][e];
            sarr[k] += q0 * kv.x + q1 * kv.y + q2 * kv.z + q3 * kv.w;
        }
    }

    // mask + softmax
    int qh = tid >> 3, qw_ = tid & 7;
    bool qa = qh < SHIFT, ql = qw_ < SHIFT;
    float mx = -3.402823466e38f;
    #pragma unroll
    for (int k = 0; k < 64; k++) {
        int kh = k >> 3, kw = k & 7;
        bool ka = kh < SHIFT, kl = kw < SHIFT;
        bool m = (!left && !top)
               || (left && top && (ql == kl) && (qa == ka))
               || (left && !top && (ql == kl))
               || (!left && top && (qa == ka));
        if (!m) sarr[k] = -3.402823466e38f;
        mx = fmaxf(mx, sarr[k]);
    }
    float sum = 0.f;
    #pragma unroll
    for (int k = 0; k < 64; k++) {
        float p = expf(sarr[k] - mx);
        sarr[k] = p;
        sum += p;
    }
    float inv = 1.0f / sum;

    // output: o[tid][e] = sum_k p[k] * v[k][e]
    float* ob = g_ow + (size_t)b * 4096 + (size_t)tid * 64;
    for (int e = 0; e < 64; e += 4) {
        float ax = 0.f, ay = 0.f, az = 0.f, aw = 0.f;
        #pragma unroll
        for (int k = 0; k < 64; k++) {
            float4 vv = *(const float4*)&vs[k][e];
            float p = sarr[k];
            ax += p * vv.x; ay += p * vv.y; az += p * vv.z; aw += p * vv.w;
        }
        float4 o4 = make_float4(ax * inv, ay * inv, az * inv, aw * inv);
        *(float4*)(ob + e) = o4;
    }
}

// ---------------------------------------------------------------------------
// K5: unwindow + unroll + head->channel transpose.
// ---------------------------------------------------------------------------
__global__ __launch_bounds__(256) void unwindow_kernel()
{
    int t = blockIdx.x;
    int n = t >> 14;
    int y = (t >> 7) & 127;
    int x = t & 127;
    int Y = (y + SHIFT) & 127, X = (x + SHIFT) & 127;
    int winbase = (Y >> 3) * 16 + (X >> 3);
    int spos = (Y & 7) * 8 + (X & 7);
    #pragma unroll
    for (int i = 0; i < 3; i++) {
        int c = threadIdx.x + 256 * i;
        int h = c >> 6, e = c & 63;
        size_t src = ((size_t)((n * NHEADS + h) * 256 + winbase)) * 4096
                   + (size_t)spos * 64 + e;
        g_oimg[(size_t)t * DM + c] = g_ow[src];
    }
}

// ---------------------------------------------------------------------------
// K6: gated GELU (exact erf):  act[t,j] = u[t,j] * gelu(u[t, DFF + j])
// ---------------------------------------------------------------------------
__global__ __launch_bounds__(256) void gelugate_kernel()
{
    size_t idx = (size_t)blockIdx.x * 256 + threadIdx.x;   // over TOKENS*DFF
    size_t t = idx >> 11;          // /2048
    int    j = (int)(idx & 2047);
    float a = g_u[t * (2 * DFF) + j];
    float g = g_u[t * (2 * DFF) + DFF + j];
    float gl = g * 0.5f * (1.0f + erff(g * 0.70710678118654752f));
    g_act[idx] = a * gl;
}

// ---------------------------------------------------------------------------
// host: launch sequence (graph-capturable; default stream only)
// ---------------------------------------------------------------------------
static void launch_sgemm(const float* A, const float* B, const float* D,
                         float* C, int M, int N, int K)
{
    dim3 grid(N / 128, M / 128);
    sgemm_nt_kernel<<<grid, 256>>>(A, B, D, C, M, N, K);
}

extern "C" void kernel_launch(void* const* d_in, const int* in_sizes, int n_in,
                              void* d_out, int out_size)
{
    const float* x          = (const float*)d_in[0];
    const float* pos        = (const float*)d_in[1];
    const float* cond       = (const float*)d_in[2];
    const float* ada1_w     = (const float*)d_in[3];
    const float* qkv_w      = (const float*)d_in[4];
    const float* attn_scale = (const float*)d_in[5];
    const float* rope_freqs = (const float*)d_in[6];
    const float* out_w      = (const float*)d_in[7];
    const float* ada2_w     = (const float*)d_in[8];
    const float* ff_up_w    = (const float*)d_in[9];
    const float* ff_down_w  = (const float*)d_in[10];
    float* out = (float*)d_out;

    float *p_scale1, *p_scale2, *p_h, *p_qkv, *p_oimg, *p_x2, *p_u, *p_act;
    cudaGetSymbolAddress((void**)&p_scale1, g_scale1);
    cudaGetSymbolAddress((void**)&p_scale2, g_scale2);
    cudaGetSymbolAddress((void**)&p_h,      g_h);
    cudaGetSymbolAddress((void**)&p_qkv,    g_qkv);
    cudaGetSymbolAddress((void**)&p_oimg,   g_oimg);
    cudaGetSymbolAddress((void**)&p_x2,     g_x2);
    cudaGetSymbolAddress((void**)&p_u,      g_u);
    cudaGetSymbolAddress((void**)&p_act,    g_act);

    // 1. ada scales (both)
    ada_kernel<<<768, 256>>>(cond, ada1_w, ada2_w);
    // 2. h1 = rmsnorm(x) * scale1
    rmsnorm_kernel<<<TOKENS, 256>>>(x, p_scale1, p_h);
    // 3. qkv = h1 @ qkv_w^T
    launch_sgemm(p_h, qkv_w, nullptr, p_qkv, TOKENS, 3 * DM, DM);
    // 4. q/k norm + rope + window scatter
    qk_transform_kernel<<<TOKENS, 384>>>(pos, attn_scale, rope_freqs);
    // 5. windowed attention
    attn_kernel<<<NWIN, 64>>>();
    // 6. unwindow
    unwindow_kernel<<<TOKENS, 256>>>();
    // 7. x2 = x + o @ out_w^T
    launch_sgemm(p_oimg, out_w, x, p_x2, TOKENS, DM, DM);
    // 8. h2 = rmsnorm(x2) * scale2
    rmsnorm_kernel<<<TOKENS, 256>>>(p_x2, p_scale2, p_h);
    // 9. u = h2 @ ff_up_w^T
    launch_sgemm(p_h, ff_up_w, nullptr, p_u, TOKENS, 2 * DFF, DM);
    // 10. act = a * gelu(g)
    gelugate_kernel<<<(TOKENS * DFF) / 256, 256>>>();
    // 11. out = x2 + act @ ff_down_w^T
    launch_sgemm(p_act, ff_down_w, p_x2, out, TOKENS, DM, DFF);
}

// round 3
// speedup vs baseline: 2.8095x; 2.8095x over previous
#include <cuda_runtime.h>
#include <cuda_bf16.h>
#include <math.h>
#include <stdint.h>

// ---------------------------------------------------------------------------
// Problem constants
// ---------------------------------------------------------------------------
#define NBATCH   4
#define HDIM     128
#define WDIM     128
#define DM       768
#define NHEADS   12
#define DHEAD    64
#define DFF      2048
#define DC       768
#define WS       8
#define SHIFT    4
#define TOKENS   (NBATCH * HDIM * WDIM)          // 65536
#define NWIN     (NBATCH * NHEADS * 16 * 16)     // 12288
#define EPSV     1e-6f

// ---------------------------------------------------------------------------
// Scratch
// ---------------------------------------------------------------------------
#define W_QKV_SZ (3 * DM * DM)
#define W_OUT_SZ (DM * DM)
#define W_UP_SZ  (2 * DFF * DM)
#define W_DN_SZ  (DM * DFF)
#define W_TOTAL  (W_QKV_SZ + W_OUT_SZ + W_UP_SZ + W_DN_SZ)

__device__ float g_scale1[NBATCH * DM];
__device__ float g_scale2[NBATCH * DM];
__device__ float g_qkv [(size_t)TOKENS * 3 * DM];
__device__ float g_qw  [(size_t)NWIN * 64 * 64];
__device__ float g_kw  [(size_t)NWIN * 64 * 64];
__device__ float g_vw  [(size_t)NWIN * 64 * 64];
__device__ float g_ow  [(size_t)NWIN * 64 * 64];
__device__ float g_x2  [(size_t)TOKENS * DM];
__device__ float g_u   [(size_t)TOKENS * 2 * DFF];

__device__ __nv_bfloat16 g_h_hi [(size_t)TOKENS * DM];
__device__ __nv_bfloat16 g_h_lo [(size_t)TOKENS * DM];
__device__ __nv_bfloat16 g_oi_hi[(size_t)TOKENS * DM];
__device__ __nv_bfloat16 g_oi_lo[(size_t)TOKENS * DM];
__device__ __nv_bfloat16 g_a_hi [(size_t)TOKENS * DFF];
__device__ __nv_bfloat16 g_a_lo [(size_t)TOKENS * DFF];
__device__ __nv_bfloat16 g_w_hi [W_TOTAL];
__device__ __nv_bfloat16 g_w_lo [W_TOTAL];

__device__ __forceinline__ void split2(float v, __nv_bfloat16* hi, __nv_bfloat16* lo) {
    __nv_bfloat16 h = __float2bfloat16(v);
    *hi = h;
    *lo = __float2bfloat16(v - __bfloat162float(h));
}

// ---------------------------------------------------------------------------
// PTX helpers (all architecture-agnostic: sm_80+ features only)
// ---------------------------------------------------------------------------
__device__ __forceinline__ uint32_t smem_to_u32(const void* p) {
    uint32_t a;
    asm("{ .reg .u64 t; cvta.to.shared.u64 t, %1; cvt.u32.u64 %0, t; }" : "=r"(a) : "l"(p));
    return a;
}
#define CP_ASYNC16(sa, gp) \
    asm volatile("cp.async.cg.shared.global [%0], [%1], 16;" :: "r"(sa), "l"(gp))
#define CP_COMMIT() asm volatile("cp.async.commit_group;" ::: "memory")
#define CP_WAIT1()  asm volatile("cp.async.wait_group 1;" ::: "memory")
#define CP_WAIT0()  asm volatile("cp.async.wait_group 0;" ::: "memory")

__device__ __forceinline__ void ldsm_x4(uint32_t& r0, uint32_t& r1, uint32_t& r2,
                                        uint32_t& r3, uint32_t addr) {
    asm volatile("ldmatrix.sync.aligned.m8n8.x4.shared.b16 {%0,%1,%2,%3}, [%4];"
                 : "=r"(r0), "=r"(r1), "=r"(r2), "=r"(r3) : "r"(addr));
}
__device__ __forceinline__ void mma16816(float c[4], const uint32_t a[4],
                                         const uint32_t b[2]) {
    asm volatile("mma.sync.aligned.m16n8k16.row.col.f32.bf16.bf16.f32 "
                 "{%0,%1,%2,%3},{%4,%5,%6,%7},{%8,%9},{%0,%1,%2,%3};"
                 : "+f"(c[0]), "+f"(c[1]), "+f"(c[2]), "+f"(c[3])
                 : "r"(a[0]), "r"(a[1]), "r"(a[2]), "r"(a[3]),
                   "r"(b[0]), "r"(b[1]));
}

// ---------------------------------------------------------------------------
// GEMM: C = (D?D:0) + A @ B^T.  A:[M,K] hi/lo bf16, B:[N,K] hi/lo bf16.
// 128x128x32 tile, 8 warps (2m x 4n), warp tile 64x32, bf16x3 compensation.
// ---------------------------------------------------------------------------
#define BKC     32
#define PADK    40                       // padded row length (bf16 elems)
#define TILE_E  (128 * PADK)             // elems per matrix tile
#define STAGE_E (4 * TILE_E)             // Ahi, Alo, Bhi, Blo
#define GEMM_SMEM (2 * STAGE_E * 2)      // bytes, double buffered = 81920

__global__ __launch_bounds__(256) void hgemm_kernel(
    const __nv_bfloat16* __restrict__ Ahi, const __nv_bfloat16* __restrict__ Alo,
    const __nv_bfloat16* __restrict__ Bhi, const __nv_bfloat16* __restrict__ Blo,
    const float* __restrict__ Dres, float* __restrict__ C,
    int M, int N, int K)
{
    extern __shared__ __align__(128) char smem[];
    const uint32_t sbase = smem_to_u32(smem);
    const int tid = threadIdx.x, lane = tid & 31, wid = tid >> 5;
    const int wm = wid >> 2, wn = wid & 3;
    const size_t bm = (size_t)blockIdx.y * 128;
    const size_t bn = (size_t)blockIdx.x * 128;

    const __nv_bfloat16* gsrc[4] = { Ahi + bm * (size_t)K, Alo + bm * (size_t)K,
                                     Bhi + bn * (size_t)K, Blo + bn * (size_t)K };

    float acc[4][4][4];
    #pragma unroll
    for (int i = 0; i < 4; i++)
        #pragma unroll
        for (int j = 0; j < 4; j++)
            #pragma unroll
            for (int l = 0; l < 4; l++) acc[i][j][l] = 0.f;

    const int row_l = tid >> 2, seg_l = tid & 3;          // load coords (idx = tid)
    const int nstage = K / BKC;

    // issue stage 'st' into buffer st&1
    auto issue = [&](int st) {
        const int k0 = st * BKC;
        const uint32_t sb = sbase + (uint32_t)((st & 1) * STAGE_E * 2);
        #pragma unroll
        for (int m_ = 0; m_ < 4; m_++) {
            #pragma unroll
            for (int j = 0; j < 2; j++) {
                int row = row_l + j * 64;
                const __nv_bfloat16* gp = gsrc[m_] + (size_t)row * K + k0 + seg_l * 8;
                uint32_t sa = sb + (uint32_t)((m_ * TILE_E + row * PADK + seg_l * 8) * 2);
                CP_ASYNC16(sa, gp);
            }
        }
        CP_COMMIT();
    };

    issue(0);
    if (nstage > 1) issue(1);

    // ldmatrix lane addressing
    const int a_r = lane & 15, a_h = (lane >> 4) << 3;
    const int b_r = (lane & 7) + ((lane & 16) >> 1);
    const int b_k = lane & 8;

    for (int st = 0; st < nstage; st++) {
        if (st + 1 < nstage) { CP_WAIT1(); } else { CP_WAIT0(); }
        __syncthreads();

        const uint32_t sb = sbase + (uint32_t)((st & 1) * STAGE_E * 2);
        const uint32_t sAhi = sb;
        const uint32_t sAlo = sb + TILE_E * 2;
        const uint32_t sBhi = sb + 2 * TILE_E * 2;
        const uint32_t sBlo = sb + 3 * TILE_E * 2;

        #pragma unroll
        for (int kk = 0; kk < BKC; kk += 16) {
            uint32_t a[4][4], al[4][4], bh[4][2], bl[4][2];
            // A hi fragments (4 m-tiles)
            #pragma unroll
            for (int mt = 0; mt < 4; mt++)
                ldsm_x4(a[mt][0], a[mt][1], a[mt][2], a[mt][3],
                        sAhi + (uint32_t)(((wm * 64 + mt * 16 + a_r) * PADK + kk + a_h) * 2));
            // B hi fragments (4 n-tiles via 2 x4-loads)
            #pragma unroll
            for (int p = 0; p < 2; p++) {
                uint32_t r0, r1, r2, r3;
                ldsm_x4(r0, r1, r2, r3,
                        sBhi + (uint32_t)(((wn * 32 + p * 16 + b_r) * PADK + kk + b_k) * 2));
                bh[p * 2][0] = r0; bh[p * 2][1] = r1;
                bh[p * 2 + 1][0] = r2; bh[p * 2 + 1][1] = r3;
            }
            #pragma unroll
            for (int mt = 0; mt < 4; mt++)
                #pragma unroll
                for (int nt = 0; nt < 4; nt++)
                    mma16816(acc[mt][nt], a[mt], bh[nt]);
            // B lo
            #pragma unroll
            for (int p = 0; p < 2; p++) {
                uint32_t r0, r1, r2, r3;
                ldsm_x4(r0, r1, r2, r3,
                        sBlo + (uint32_t)(((wn * 32 + p * 16 + b_r) * PADK + kk + b_k) * 2));
                bl[p * 2][0] = r0; bl[p * 2][1] = r1;
                bl[p * 2 + 1][0] = r2; bl[p * 2 + 1][1] = r3;
            }
            #pragma unroll
            for (int mt = 0; mt < 4; mt++)
                #pragma unroll
                for (int nt = 0; nt < 4; nt++)
                    mma16816(acc[mt][nt], a[mt], bl[nt]);
            // A lo
            #pragma unroll
            for (int mt = 0; mt < 4; mt++)
                ldsm_x4(al[mt][0], al[mt][1], al[mt][2], al[mt][3],
                        sAlo + (uint32_t)(((wm * 64 + mt * 16 + a_r) * PADK + kk + a_h) * 2));
            #pragma unroll
            for (int mt = 0; mt < 4; mt++)
                #pragma unroll
                for (int nt = 0; nt < 4; nt++)
                    mma16816(acc[mt][nt], al[mt], bh[nt]);
        }
        __syncthreads();
        if (st + 2 < nstage) issue(st + 2);
    }

    // epilogue
    const int er = lane >> 2, ec = (lane & 3) * 2;
    #pragma unroll
    for (int mt = 0; mt < 4; mt++) {
        size_t row0 = bm + wm * 64 + mt * 16 + er;
        #pragma unroll
        for (int nt = 0; nt < 4; nt++) {
            size_t col = bn + wn * 32 + nt * 8 + ec;
            float* p0 = C + row0 * (size_t)N + col;
            float* p1 = C + (row0 + 8) * (size_t)N + col;
            float2 v0 = make_float2(acc[mt][nt][0], acc[mt][nt][1]);
            float2 v1 = make_float2(acc[mt][nt][2], acc[mt][nt][3]);
            if (Dres) {
                const float2 d0 = *(const float2*)(Dres + row0 * (size_t)N + col);
                const float2 d1 = *(const float2*)(Dres + (row0 + 8) * (size_t)N + col);
                v0.x += d0.x; v0.y += d0.y; v1.x += d1.x; v1.y += d1.y;
            }
            *(float2*)p0 = v0;
            *(float2*)p1 = v1;
        }
    }
}

// ---------------------------------------------------------------------------
// K0: ada scales
// ---------------------------------------------------------------------------
__global__ void ada_kernel(const float* __restrict__ cond,
                           const float* __restrict__ w1,
                           const float* __restrict__ w2)
{
    int gw   = (blockIdx.x * blockDim.x + threadIdx.x) >> 5;
    int lane = threadIdx.x & 31;
    if (gw >= 2 * NBATCH * DM) return;
    int which = gw / (NBATCH * DM);
    int rem   = gw % (NBATCH * DM);
    int n = rem / DM, d = rem % DM;
    const float* w  = which ? w2 : w1;
    const float* cr = cond + n * DC;
    const float* wr = w + (size_t)d * DC;
    float s = 0.f;
    for (int i = lane; i < DC; i += 32) s += cr[i] * wr[i];
    #pragma unroll
    for (int o = 16; o; o >>= 1) s += __shfl_xor_sync(0xffffffffu, s, o);
    if (lane == 0) (which ? g_scale2 : g_scale1)[rem] = s + 1.0f;
}

// ---------------------------------------------------------------------------
// K1: RMSNorm * ada -> bf16 hi/lo
// ---------------------------------------------------------------------------
__global__ __launch_bounds__(256) void rmsnorm_kernel(const float* __restrict__ x,
                                                      const float* __restrict__ scale)
{
    int t = blockIdx.x;
    int n = t >> 14;
    const float* xr = x + (size_t)t * DM;
    float v[3]; float ss = 0.f;
    #pragma unroll
    for (int i = 0; i < 3; i++) { v[i] = xr[threadIdx.x + 256 * i]; ss += v[i] * v[i]; }
    __shared__ float red[8];
    #pragma unroll
    for (int o = 16; o; o >>= 1) ss += __shfl_xor_sync(0xffffffffu, ss, o);
    if ((threadIdx.x & 31) == 0) red[threadIdx.x >> 5] = ss;
    __syncthreads();
    if (threadIdx.x == 0) {
        float r = 0.f;
        #pragma unroll
        for (int i = 0; i < 8; i++) r += red[i];
        red[0] = r;
    }
    __syncthreads();
    float inv = rsqrtf(red[0] * (1.0f / DM) + EPSV);
    const float* sc = scale + (size_t)n * DM;
    #pragma unroll
    for (int i = 0; i < 3; i++) {
        int c = threadIdx.x + 256 * i;
        float o = v[i] * sc[c] * inv;
        split2(o, &g_h_hi[(size_t)t * DM + c], &g_h_lo[(size_t)t * DM + c]);
    }
}

// ---------------------------------------------------------------------------
// K2: weight split
// ---------------------------------------------------------------------------
__global__ __launch_bounds__(256) void wsplit_kernel(const float* __restrict__ w,
                                                     __nv_bfloat16* __restrict__ hi,
                                                     __nv_bfloat16* __restrict__ lo, int n)
{
    int i = blockIdx.x * 256 + threadIdx.x;
    if (i >= n) return;
    split2(w[i], &hi[i], &lo[i]);
}

// ---------------------------------------------------------------------------
// K3: q/k norm + RoPE + window scatter
// ---------------------------------------------------------------------------
__global__ __launch_bounds__(384) void qk_transform_kernel(const float* __restrict__ pos,
                                                           const float* __restrict__ attn_scale,
                                                           const float* __restrict__ rope_freqs)
{
    int t = blockIdx.x;
    int h = threadIdx.x >> 5;
    int l = threadIdx.x & 31;
    int n = t >> 14;
    int y = (t >> 7) & 127;
    int x = t & 127;

    const float* base = g_qkv + (size_t)t * (3 * DM) + h * DHEAD;
    float q0 = base[l],            q1 = base[l + 32];
    float k0 = base[DM + l],       k1 = base[DM + l + 32];
    float v0 = base[2 * DM + l],   v1 = base[2 * DM + l + 32];

    float sq = q0 * q0 + q1 * q1;
    float sk = k0 * k0 + k1 * k1;
    #pragma unroll
    for (int o = 16; o; o >>= 1) {
        sq += __shfl_xor_sync(0xffffffffu, sq, o);
        sk += __shfl_xor_sync(0xffffffffu, sk, o);
    }
    float ssh = sqrtf(attn_scale[h]);
    float rq = ssh * rsqrtf(sq + EPSV);
    float rk = ssh * rsqrtf(sk + EPSV);
    q0 *= rq; q1 *= rq; k0 *= rk; k1 *= rk;

    float p0 = pos[(size_t)t * 2 + 0];
    float p1 = pos[(size_t)t * 2 + 1];
    int f = l & 15;
    float freq = rope_freqs[h * 8 + (f & 7)];
    float th = (f < 8 ? p0 : p1) * freq;
    float c = cosf(th), s = sinf(th);
    float qp = __shfl_xor_sync(0xffffffffu, q0, 16);
    float kp = __shfl_xor_sync(0xffffffffu, k0, 16);
    if (l < 16) { q0 = q0 * c - qp * s; k0 = k0 * c - kp * s; }
    else        { q0 = q0 * c + qp * s; k0 = k0 * c + kp * s; }

    int Y = (y + SHIFT) & 127, X = (x + SHIFT) & 127;
    int win  = ((n * NHEADS + h) * 16 + (Y >> 3)) * 16 + (X >> 3);
    int spos = (Y & 7) * 8 + (X & 7);
    size_t o = (size_t)win * 4096 + (size_t)spos * 64 + l;
    g_qw[o] = q0; g_qw[o + 32] = q1;
    g_kw[o] = k0; g_kw[o + 32] = k1;
    g_vw[o] = v0; g_vw[o + 32] = v1;
}

// ---------------------------------------------------------------------------
// K4: windowed attention
// ---------------------------------------------------------------------------
#define QT(e, r) qT[(e) * 64 + (((r) + (e)) & 63)]

__global__ __launch_bounds__(64) void attn_kernel()
{
    __shared__ float qT[64 * 64];
    __shared__ float ks[64][64];
    __shared__ float vs[64][64];

    int b   = blockIdx.x;
    int w   = b & 255;
    int wwi = w & 15, whi = (w >> 4) & 15;
    bool left = (wwi == 0), top = (whi == 0);

    const float* qb = g_qw + (size_t)b * 4096;
    const float* kb = g_kw + (size_t)b * 4096;
    const float* vb = g_vw + (size_t)b * 4096;
    int tid = threadIdx.x;

    for (int i = tid; i < 1024; i += 64) {
        int r = i >> 4, c = (i & 15) << 2;
        float4 kv = *(const float4*)(kb + (i << 2));
        *(float4*)&ks[r][c] = kv;
        float4 vv = *(const float4*)(vb + (i << 2));
        *(float4*)&vs[r][c] = vv;
        float4 qv = *(const float4*)(qb + (i << 2));
        QT(c + 0, r) = qv.x; QT(c + 1, r) = qv.y;
        QT(c + 2, r) = qv.z; QT(c + 3, r) = qv.w;
    }
    __syncthreads();

    float sarr[64];
    #pragma unroll
    for (int k = 0; k < 64; k++) sarr[k] = 0.f;
    for (int e = 0; e < 64; e += 4) {
        float q0 = QT(e + 0, tid), q1 = QT(e + 1, tid);
        float q2 = QT(e + 2, tid), q3 = QT(e + 3, tid);
        #pragma unroll
        for (int k = 0; k < 64; k++) {
            float4 kv = *(const float4*)&ks[k][e];
            sarr[k] += q0 * kv.x + q1 * kv.y + q2 * kv.z + q3 * kv.w;
        }
    }

    int qh = tid >> 3, qw_ = tid & 7;
    bool qa = qh < SHIFT, ql = qw_ < SHIFT;
    float mx = -3.402823466e38f;
    #pragma unroll
    for (int k = 0; k < 64; k++) {
        int kh = k >> 3, kw = k & 7;
        bool ka = kh < SHIFT, kl = kw < SHIFT;
        bool m = (!left && !top)
               || (left && top && (ql == kl) && (qa == ka))
               || (left && !top && (ql == kl))
               || (!left && top && (qa == ka));
        if (!m) sarr[k] = -3.402823466e38f;
        mx = fmaxf(mx, sarr[k]);
    }
    float sum = 0.f;
    #pragma unroll
    for (int k = 0; k < 64; k++) {
        float p = expf(sarr[k] - mx);
        sarr[k] = p;
        sum += p;
    }
    float inv = 1.0f / sum;

    float* ob = g_ow + (size_t)b * 4096 + (size_t)tid * 64;
    for (int e = 0; e < 64; e += 4) {
        float ax = 0.f, ay = 0.f, az = 0.f, aw = 0.f;
        #pragma unroll
        for (int k = 0; k < 64; k++) {
            float4 vv = *(const float4*)&vs[k][e];
            float p = sarr[k];
            ax += p * vv.x; ay += p * vv.y; az += p * vv.z; aw += p * vv.w;
        }
        float4 o4 = make_float4(ax * inv, ay * inv, az * inv, aw * inv);
        *(float4*)(ob + e) = o4;
    }
}

// ---------------------------------------------------------------------------
// K5: unwindow -> bf16 hi/lo
// ---------------------------------------------------------------------------
__global__ __launch_bounds__(256) void unwindow_kernel()
{
    int t = blockIdx.x;
    int n = t >> 14;
    int y = (t >> 7) & 127;
    int x = t & 127;
    int Y = (y + SHIFT) & 127, X = (x + SHIFT) & 127;
    int winbase = (Y >> 3) * 16 + (X >> 3);
    int spos = (Y & 7) * 8 + (X & 7);
    #pragma unroll
    for (int i = 0; i < 3; i++) {
        int c = threadIdx.x + 256 * i;
        int h = c >> 6, e = c & 63;
        size_t src = ((size_t)((n * NHEADS + h) * 256 + winbase)) * 4096
                   + (size_t)spos * 64 + e;
        split2(g_ow[src], &g_oi_hi[(size_t)t * DM + c], &g_oi_lo[(size_t)t * DM + c]);
    }
}

// ---------------------------------------------------------------------------
// K6: gated GELU -> bf16 hi/lo
// ---------------------------------------------------------------------------
__global__ __launch_bounds__(256) void gelugate_kernel()
{
    size_t idx = (size_t)blockIdx.x * 256 + threadIdx.x;
    size_t t = idx >> 11;
    int    j = (int)(idx & 2047);
    float a = g_u[t * (2 * DFF) + j];
    float g = g_u[t * (2 * DFF) + DFF + j];
    float gl = g * 0.5f * (1.0f + erff(g * 0.70710678118654752f));
    split2(a * gl, &g_a_hi[idx], &g_a_lo[idx]);
}

// ---------------------------------------------------------------------------
// host
// ---------------------------------------------------------------------------
static void launch_hgemm(const __nv_bfloat16* Ah, const __nv_bfloat16* Al,
                         const __nv_bfloat16* Bh, const __nv_bfloat16* Bl,
                         const float* D, float* C, int M, int N, int K)
{
    dim3 grid(N / 128, M / 128);
    hgemm_kernel<<<grid, 256, GEMM_SMEM>>>(Ah, Al, Bh, Bl, D, C, M, N, K);
}

extern "C" void kernel_launch(void* const* d_in, const int* in_sizes, int n_in,
                              void* d_out, int out_size)
{
    const float* x          = (const float*)d_in[0];
    const float* pos        = (const float*)d_in[1];
    const float* cond       = (const float*)d_in[2];
    const float* ada1_w     = (const float*)d_in[3];
    const float* qkv_w      = (const float*)d_in[4];
    const float* attn_scale = (const float*)d_in[5];
    const float* rope_freqs = (const float*)d_in[6];
    const float* out_w      = (const float*)d_in[7];
    const float* ada2_w     = (const float*)d_in[8];
    const float* ff_up_w    = (const float*)d_in[9];
    const float* ff_down_w  = (const float*)d_in[10];
    float* out = (float*)d_out;

    cudaFuncSetAttribute(hgemm_kernel, cudaFuncAttributeMaxDynamicSharedMemorySize, GEMM_SMEM);

    float *p_scale1, *p_scale2, *p_qkv, *p_x2, *p_u;
    __nv_bfloat16 *p_hh, *p_hl, *p_oih, *p_oil, *p_ah, *p_al, *p_wh, *p_wl;
    cudaGetSymbolAddress((void**)&p_scale1, g_scale1);
    cudaGetSymbolAddress((void**)&p_scale2, g_scale2);
    cudaGetSymbolAddress((void**)&p_qkv,    g_qkv);
    cudaGetSymbolAddress((void**)&p_x2,     g_x2);
    cudaGetSymbolAddress((void**)&p_u,      g_u);
    cudaGetSymbolAddress((void**)&p_hh,     g_h_hi);
    cudaGetSymbolAddress((void**)&p_hl,     g_h_lo);
    cudaGetSymbolAddress((void**)&p_oih,    g_oi_hi);
    cudaGetSymbolAddress((void**)&p_oil,    g_oi_lo);
    cudaGetSymbolAddress((void**)&p_ah,     g_a_hi);
    cudaGetSymbolAddress((void**)&p_al,     g_a_lo);
    cudaGetSymbolAddress((void**)&p_wh,     g_w_hi);
    cudaGetSymbolAddress((void**)&p_wl,     g_w_lo);

    const int OQKV = 0;
    const int OOUT = OQKV + W_QKV_SZ;
    const int OUP  = OOUT + W_OUT_SZ;
    const int ODN  = OUP + W_UP_SZ;

    wsplit_kernel<<<(W_QKV_SZ + 255) / 256, 256>>>(qkv_w,     p_wh + OQKV, p_wl + OQKV, W_QKV_SZ);
    wsplit_kernel<<<(W_OUT_SZ + 255) / 256, 256>>>(out_w,     p_wh + OOUT, p_wl + OOUT, W_OUT_SZ);
    wsplit_kernel<<<(W_UP_SZ  + 255) / 256, 256>>>(ff_up_w,   p_wh + OUP,  p_wl + OUP,  W_UP_SZ);
    wsplit_kernel<<<(W_DN_SZ  + 255) / 256, 256>>>(ff_down_w, p_wh + ODN,  p_wl + ODN,  W_DN_SZ);

    ada_kernel<<<768, 256>>>(cond, ada1_w, ada2_w);
    rmsnorm_kernel<<<TOKENS, 256>>>(x, p_scale1);
    launch_hgemm(p_hh, p_hl, p_wh + OQKV, p_wl + OQKV, nullptr, p_qkv, TOKENS, 3 * DM, DM);
    qk_transform_kernel<<<TOKENS, 384>>>(pos, attn_scale, rope_freqs);
    attn_kernel<<<NWIN, 64>>>();
    unwindow_kernel<<<TOKENS, 256>>>();
    launch_hgemm(p_oih, p_oil, p_wh + OOUT, p_wl + OOUT, x, p_x2, TOKENS, DM, DM);
    rmsnorm_kernel<<<TOKENS, 256>>>(p_x2, p_scale2);
    launch_hgemm(p_hh, p_hl, p_wh + OUP, p_wl + OUP, nullptr, p_u, TOKENS, 2 * DFF, DM);
    gelugate_kernel<<<(TOKENS * DFF) / 256, 256>>>();
    launch_hgemm(p_ah, p_al, p_wh + ODN, p_wl + ODN, p_x2, out, TOKENS, DM, DFF);
}

// round 4
// speedup vs baseline: 2.8429x; 1.0119x over previous
#include <cuda_runtime.h>
#include <cuda_bf16.h>
#include <math.h>
#include <stdint.h>

// ---------------------------------------------------------------------------
// Problem constants
// ---------------------------------------------------------------------------
#define NBATCH   4
#define HDIM     128
#define WDIM     128
#define DM       768
#define NHEADS   12
#define DHEAD    64
#define DFF      2048
#define DC       768
#define WS       8
#define SHIFT    4
#define TOKENS   (NBATCH * HDIM * WDIM)          // 65536
#define NWIN     (NBATCH * NHEADS * 16 * 16)     // 12288
#define EPSV     1e-6f

// ---------------------------------------------------------------------------
// Scratch
// ---------------------------------------------------------------------------
#define W_QKV_SZ (3 * DM * DM)
#define W_OUT_SZ (DM * DM)
#define W_UP_SZ  (2 * DFF * DM)
#define W_DN_SZ  (DM * DFF)
#define W_TOTAL  (W_QKV_SZ + W_OUT_SZ + W_UP_SZ + W_DN_SZ)

__device__ float g_scale1[NBATCH * DM];
__device__ float g_scale2[NBATCH * DM];
__device__ float g_qkv [(size_t)TOKENS * 2 * DM];     // q,k only (ldc=1536)
__device__ float g_qw  [(size_t)NWIN * 64 * 64];
__device__ float g_kw  [(size_t)NWIN * 64 * 64];
__device__ float g_vw  [(size_t)NWIN * 64 * 64];
__device__ float g_ow  [(size_t)NWIN * 64 * 64];
__device__ float g_x2  [(size_t)TOKENS * DM];

__device__ __nv_bfloat16 g_h_hi [(size_t)TOKENS * DM];
__device__ __nv_bfloat16 g_h_lo [(size_t)TOKENS * DM];
__device__ __nv_bfloat16 g_oi_hi[(size_t)TOKENS * DM];
__device__ __nv_bfloat16 g_oi_lo[(size_t)TOKENS * DM];
__device__ __nv_bfloat16 g_a_hi [(size_t)TOKENS * DFF];
__device__ __nv_bfloat16 g_a_lo [(size_t)TOKENS * DFF];
__device__ __nv_bfloat16 g_w_hi [W_TOTAL];
__device__ __nv_bfloat16 g_w_lo [W_TOTAL];

__device__ __forceinline__ void split2(float v, __nv_bfloat16* hi, __nv_bfloat16* lo) {
    __nv_bfloat16 h = __float2bfloat16(v);
    *hi = h;
    *lo = __float2bfloat16(v - __bfloat162float(h));
}

// ---------------------------------------------------------------------------
// PTX helpers (sm_80+ features only; legal under compute_103)
// ---------------------------------------------------------------------------
__device__ __forceinline__ uint32_t smem_to_u32(const void* p) {
    uint32_t a;
    asm("{ .reg .u64 t; cvta.to.shared.u64 t, %1; cvt.u32.u64 %0, t; }" : "=r"(a) : "l"(p));
    return a;
}
#define CP_ASYNC16(sa, gp) \
    asm volatile("cp.async.cg.shared.global [%0], [%1], 16;" :: "r"(sa), "l"(gp))
#define CP_COMMIT() asm volatile("cp.async.commit_group;" ::: "memory")
#define CP_WAIT1()  asm volatile("cp.async.wait_group 1;" ::: "memory")
#define CP_WAIT0()  asm volatile("cp.async.wait_group 0;" ::: "memory")

__device__ __forceinline__ void ldsm_x4(uint32_t& r0, uint32_t& r1, uint32_t& r2,
                                        uint32_t& r3, uint32_t addr) {
    asm volatile("ldmatrix.sync.aligned.m8n8.x4.shared.b16 {%0,%1,%2,%3}, [%4];"
                 : "=r"(r0), "=r"(r1), "=r"(r2), "=r"(r3) : "r"(addr));
}
__device__ __forceinline__ void mma16816(float c[4], const uint32_t a[4],
                                         const uint32_t b[2]) {
    asm volatile("mma.sync.aligned.m16n8k16.row.col.f32.bf16.bf16.f32 "
                 "{%0,%1,%2,%3},{%4,%5,%6,%7},{%8,%9},{%0,%1,%2,%3};"
                 : "+f"(c[0]), "+f"(c[1]), "+f"(c[2]), "+f"(c[3])
                 : "r"(a[0]), "r"(a[1]), "r"(a[2]), "r"(b[0]), "r"(b[1]),
                   "r"(a[3])  // placeholder to keep operand order -- fixed below
                 );
}

// NOTE: correct operand order version (used everywhere)
__device__ __forceinline__ void mma_bf16(float c[4], const uint32_t a[4],
                                         const uint32_t b[2]) {
    asm volatile("mma.sync.aligned.m16n8k16.row.col.f32.bf16.bf16.f32 "
                 "{%0,%1,%2,%3},{%4,%5,%6,%7},{%8,%9},{%0,%1,%2,%3};"
                 : "+f"(c[0]), "+f"(c[1]), "+f"(c[2]), "+f"(c[3])
                 : "r"(a[0]), "r"(a[1]), "r"(a[2]), "r"(a[3]),
                   "r"(b[0]), "r"(b[1]));
}

// window-scatter address helper (roll +4,+4 then 8x8 windows)
__device__ __forceinline__ size_t win_addr(int t, int h, int e) {
    int n = t >> 14;
    int y = (t >> 7) & 127;
    int x = t & 127;
    int Y = (y + SHIFT) & 127, X = (x + SHIFT) & 127;
    int wyx  = ((Y >> 3) << 4) + (X >> 3);
    int spos = ((Y & 7) << 3) + (X & 7);
    return ((size_t)((n * NHEADS + h) * 256 + wyx)) * 4096 + (size_t)spos * 64 + e;
}

// ---------------------------------------------------------------------------
// GEMM: 128x128x32 tile, 8 warps (2m x 4n), warp tile 64x32, bf16x3.
// mode 0: C[row*ldc+col] = (D?D:0) + A@B^T
// mode 1: fused gated-GELU epilogue -> g_a_hi/g_a_lo (weights pre-interleaved)
// mode 2: qkv epilogue: cols<1536 -> C (ldc), cols>=1536 -> scatter V to g_vw
// ---------------------------------------------------------------------------
#define BKC     32
#define PADK    40
#define TILE_E  (128 * PADK)
#define STAGE_E (4 * TILE_E)
#define GEMM_SMEM (2 * STAGE_E * 2)

__global__ __launch_bounds__(256) void hgemm_kernel(
    const __nv_bfloat16* __restrict__ Ahi, const __nv_bfloat16* __restrict__ Alo,
    const __nv_bfloat16* __restrict__ Bhi, const __nv_bfloat16* __restrict__ Blo,
    const float* __restrict__ Dres, float* __restrict__ C,
    int M, int N, int K, int ldc, int mode)
{
    extern __shared__ __align__(128) char smem[];
    const uint32_t sbase = smem_to_u32(smem);
    const int tid = threadIdx.x, lane = tid & 31, wid = tid >> 5;
    const int wm = wid >> 2, wn = wid & 3;
    const size_t bm = (size_t)blockIdx.y * 128;
    const size_t bn = (size_t)blockIdx.x * 128;

    const __nv_bfloat16* gsrc[4] = { Ahi + bm * (size_t)K, Alo + bm * (size_t)K,
                                     Bhi + bn * (size_t)K, Blo + bn * (size_t)K };

    float acc[4][4][4];
    #pragma unroll
    for (int i = 0; i < 4; i++)
        #pragma unroll
        for (int j = 0; j < 4; j++)
            #pragma unroll
            for (int l = 0; l < 4; l++) acc[i][j][l] = 0.f;

    const int row_l = tid >> 2, seg_l = tid & 3;
    const int nstage = K / BKC;

    auto issue = [&](int st) {
        const int k0 = st * BKC;
        const uint32_t sb = sbase + (uint32_t)((st & 1) * STAGE_E * 2);
        #pragma unroll
        for (int m_ = 0; m_ < 4; m_++) {
            #pragma unroll
            for (int j = 0; j < 2; j++) {
                int row = row_l + j * 64;
                const __nv_bfloat16* gp = gsrc[m_] + (size_t)row * K + k0 + seg_l * 8;
                uint32_t sa = sb + (uint32_t)((m_ * TILE_E + row * PADK + seg_l * 8) * 2);
                CP_ASYNC16(sa, gp);
            }
        }
        CP_COMMIT();
    };

    issue(0);
    if (nstage > 1) issue(1);

    const int a_r = lane & 15, a_h = (lane >> 4) << 3;
    const int b_r = (lane & 7) + ((lane & 16) >> 1);
    const int b_k = lane & 8;

    for (int st = 0; st < nstage; st++) {
        if (st + 1 < nstage) { CP_WAIT1(); } else { CP_WAIT0(); }
        __syncthreads();

        const uint32_t sb = sbase + (uint32_t)((st & 1) * STAGE_E * 2);
        const uint32_t sAhi = sb;
        const uint32_t sAlo = sb + TILE_E * 2;
        const uint32_t sBhi = sb + 2 * TILE_E * 2;
        const uint32_t sBlo = sb + 3 * TILE_E * 2;

        #pragma unroll
        for (int kk = 0; kk < BKC; kk += 16) {
            uint32_t a[4][4], al[4][4], bh[4][2], bl[4][2];
            #pragma unroll
            for (int mt = 0; mt < 4; mt++)
                ldsm_x4(a[mt][0], a[mt][1], a[mt][2], a[mt][3],
                        sAhi + (uint32_t)(((wm * 64 + mt * 16 + a_r) * PADK + kk + a_h) * 2));
            #pragma unroll
            for (int p = 0; p < 2; p++) {
                uint32_t r0, r1, r2, r3;
                ldsm_x4(r0, r1, r2, r3,
                        sBhi + (uint32_t)(((wn * 32 + p * 16 + b_r) * PADK + kk + b_k) * 2));
                bh[p * 2][0] = r0; bh[p * 2][1] = r1;
                bh[p * 2 + 1][0] = r2; bh[p * 2 + 1][1] = r3;
            }
            #pragma unroll
            for (int mt = 0; mt < 4; mt++)
                #pragma unroll
                for (int nt = 0; nt < 4; nt++)
                    mma_bf16(acc[mt][nt], a[mt], bh[nt]);
            #pragma unroll
            for (int p = 0; p < 2; p++) {
                uint32_t r0, r1, r2, r3;
                ldsm_x4(r0, r1, r2, r3,
                        sBlo + (uint32_t)(((wn * 32 + p * 16 + b_r) * PADK + kk + b_k) * 2));
                bl[p * 2][0] = r0; bl[p * 2][1] = r1;
                bl[p * 2 + 1][0] = r2; bl[p * 2 + 1][1] = r3;
            }
            #pragma unroll
            for (int mt = 0; mt < 4; mt++)
                #pragma unroll
                for (int nt = 0; nt < 4; nt++)
                    mma_bf16(acc[mt][nt], a[mt], bl[nt]);
            #pragma unroll
            for (int mt = 0; mt < 4; mt++)
                ldsm_x4(al[mt][0], al[mt][1], al[mt][2], al[mt][3],
                        sAlo + (uint32_t)(((wm * 64 + mt * 16 + a_r) * PADK + kk + a_h) * 2));
            #pragma unroll
            for (int mt = 0; mt < 4; mt++)
                #pragma unroll
                for (int nt = 0; nt < 4; nt++)
                    mma_bf16(acc[mt][nt], al[mt], bh[nt]);
        }
        __syncthreads();
        if (st + 2 < nstage) issue(st + 2);
    }

    // ---------------- epilogue ----------------
    const int er = lane >> 2, ec = (lane & 3) * 2;

    if (mode == 1) {
        // fused gated GELU: col pair (even,odd) = (a_j, g_j); j = col/2
        #pragma unroll
        for (int mt = 0; mt < 4; mt++) {
            size_t r0 = bm + wm * 64 + mt * 16 + er;
            size_t r1 = r0 + 8;
            #pragma unroll
            for (int nt = 0; nt < 4; nt++) {
                int col = (int)bn + wn * 32 + nt * 8 + ec;
                int j = col >> 1;
                float a0 = acc[mt][nt][0], gg0 = acc[mt][nt][1];
                float a1 = acc[mt][nt][2], gg1 = acc[mt][nt][3];
                float v0 = a0 * (gg0 * 0.5f * (1.0f + erff(gg0 * 0.70710678118654752f)));
                float v1 = a1 * (gg1 * 0.5f * (1.0f + erff(gg1 * 0.70710678118654752f)));
                split2(v0, &g_a_hi[r0 * DFF + j], &g_a_lo[r0 * DFF + j]);
                split2(v1, &g_a_hi[r1 * DFF + j], &g_a_lo[r1 * DFF + j]);
            }
        }
        return;
    }

    if (mode == 2 && bn >= 1536) {
        // V region: scatter straight into windowed layout
        #pragma unroll
        for (int mt = 0; mt < 4; mt++) {
            int t0 = (int)bm + wm * 64 + mt * 16 + er;
            int t1 = t0 + 8;
            #pragma unroll
            for (int nt = 0; nt < 4; nt++) {
                int col = (int)bn + wn * 32 + nt * 8 + ec;
                int h = (col - 1536) >> 6;
                int e = col & 63;
                float2 v0 = make_float2(acc[mt][nt][0], acc[mt][nt][1]);
                float2 v1 = make_float2(acc[mt][nt][2], acc[mt][nt][3]);
                *(float2*)&g_vw[win_addr(t0, h, e)] = v0;
                *(float2*)&g_vw[win_addr(t1, h, e)] = v1;
            }
        }
        return;
    }

    // plain / q,k region
    #pragma unroll
    for (int mt = 0; mt < 4; mt++) {
        size_t row0 = bm + wm * 64 + mt * 16 + er;
        #pragma unroll
        for (int nt = 0; nt < 4; nt++) {
            size_t col = bn + wn * 32 + nt * 8 + ec;
            if (mode == 2 && col >= 1536) continue;
            float* p0 = C + row0 * (size_t)ldc + col;
            float* p1 = C + (row0 + 8) * (size_t)ldc + col;
            float2 v0 = make_float2(acc[mt][nt][0], acc[mt][nt][1]);
            float2 v1 = make_float2(acc[mt][nt][2], acc[mt][nt][3]);
            if (Dres) {
                const float2 d0 = *(const float2*)(Dres + row0 * (size_t)ldc + col);
                const float2 d1 = *(const float2*)(Dres + (row0 + 8) * (size_t)ldc + col);
                v0.x += d0.x; v0.y += d0.y; v1.x += d1.x; v1.y += d1.y;
            }
            *(float2*)p0 = v0;
            *(float2*)p1 = v1;
        }
    }
}

// ---------------------------------------------------------------------------
// K0: ada scales
// ---------------------------------------------------------------------------
__global__ void ada_kernel(const float* __restrict__ cond,
                           const float* __restrict__ w1,
                           const float* __restrict__ w2)
{
    int gw   = (blockIdx.x * blockDim.x + threadIdx.x) >> 5;
    int lane = threadIdx.x & 31;
    if (gw >= 2 * NBATCH * DM) return;
    int which = gw / (NBATCH * DM);
    int rem   = gw % (NBATCH * DM);
    int n = rem / DM, d = rem % DM;
    const float* w  = which ? w2 : w1;
    const float* cr = cond + n * DC;
    const float* wr = w + (size_t)d * DC;
    float s = 0.f;
    for (int i = lane; i < DC; i += 32) s += cr[i] * wr[i];
    #pragma unroll
    for (int o = 16; o; o >>= 1) s += __shfl_xor_sync(0xffffffffu, s, o);
    if (lane == 0) (which ? g_scale2 : g_scale1)[rem] = s + 1.0f;
}

// ---------------------------------------------------------------------------
// K1: RMSNorm * ada -> bf16 hi/lo
// ---------------------------------------------------------------------------
__global__ __launch_bounds__(256) void rmsnorm_kernel(const float* __restrict__ x,
                                                      const float* __restrict__ scale)
{
    int t = blockIdx.x;
    int n = t >> 14;
    const float* xr = x + (size_t)t * DM;
    float v[3]; float ss = 0.f;
    #pragma unroll
    for (int i = 0; i < 3; i++) { v[i] = xr[threadIdx.x + 256 * i]; ss += v[i] * v[i]; }
    __shared__ float red[8];
    #pragma unroll
    for (int o = 16; o; o >>= 1) ss += __shfl_xor_sync(0xffffffffu, ss, o);
    if ((threadIdx.x & 31) == 0) red[threadIdx.x >> 5] = ss;
    __syncthreads();
    if (threadIdx.x == 0) {
        float r = 0.f;
        #pragma unroll
        for (int i = 0; i < 8; i++) r += red[i];
        red[0] = r;
    }
    __syncthreads();
    float inv = rsqrtf(red[0] * (1.0f / DM) + EPSV);
    const float* sc = scale + (size_t)n * DM;
    #pragma unroll
    for (int i = 0; i < 3; i++) {
        int c = threadIdx.x + 256 * i;
        float o = v[i] * sc[c] * inv;
        split2(o, &g_h_hi[(size_t)t * DM + c], &g_h_lo[(size_t)t * DM + c]);
    }
}

// ---------------------------------------------------------------------------
// K2: weight split (optional row interleave for ff_up gating)
// ---------------------------------------------------------------------------
__global__ __launch_bounds__(256) void wsplit_kernel(const float* __restrict__ w,
                                                     __nv_bfloat16* __restrict__ hi,
                                                     __nv_bfloat16* __restrict__ lo,
                                                     int n, int rowlen, int perm)
{
    int i = blockIdx.x * 256 + threadIdx.x;
    if (i >= n) return;
    int dst = i;
    if (perm) {
        int r = i / rowlen, c = i % rowlen;
        int dr = (r < DFF) ? (2 * r) : (2 * (r - DFF) + 1);
        dst = dr * rowlen + c;
    }
    split2(w[i], &hi[dst], &lo[dst]);
}

// ---------------------------------------------------------------------------
// K3: q/k norm + RoPE + window scatter (v handled in GEMM epilogue)
// ---------------------------------------------------------------------------
__global__ __launch_bounds__(384) void qk_transform_kernel(const float* __restrict__ pos,
                                                           const float* __restrict__ attn_scale,
                                                           const float* __restrict__ rope_freqs)
{
    int t = blockIdx.x;
    int h = threadIdx.x >> 5;
    int l = threadIdx.x & 31;

    const float* base = g_qkv + (size_t)t * (2 * DM) + h * DHEAD;
    float q0 = base[l],          q1 = base[l + 32];
    float k0 = base[DM + l],     k1 = base[DM + l + 32];

    float sq = q0 * q0 + q1 * q1;
    float sk = k0 * k0 + k1 * k1;
    #pragma unroll
    for (int o = 16; o; o >>= 1) {
        sq += __shfl_xor_sync(0xffffffffu, sq, o);
        sk += __shfl_xor_sync(0xffffffffu, sk, o);
    }
    float ssh = sqrtf(attn_scale[h]);
    float rq = ssh * rsqrtf(sq + EPSV);
    float rk = ssh * rsqrtf(sk + EPSV);
    q0 *= rq; q1 *= rq; k0 *= rk; k1 *= rk;

    float p0 = pos[(size_t)t * 2 + 0];
    float p1 = pos[(size_t)t * 2 + 1];
    int f = l & 15;
    float freq = rope_freqs[h * 8 + (f & 7)];
    float th = (f < 8 ? p0 : p1) * freq;
    float c = cosf(th), s = sinf(th);
    float qp = __shfl_xor_sync(0xffffffffu, q0, 16);
    float kp = __shfl_xor_sync(0xffffffffu, k0, 16);
    if (l < 16) { q0 = q0 * c - qp * s; k0 = k0 * c - kp * s; }
    else        { q0 = q0 * c + qp * s; k0 = k0 * c + kp * s; }

    size_t o = win_addr(t, h, l);
    g_qw[o] = q0; g_qw[o + 32] = q1;
    g_kw[o] = k0; g_kw[o + 32] = k1;
}

// ---------------------------------------------------------------------------
// K4: windowed attention (fp32, __expf softmax)
// ---------------------------------------------------------------------------
#define QT(e, r) qT[(e) * 64 + (((r) + (e)) & 63)]

__global__ __launch_bounds__(64) void attn_kernel()
{
    __shared__ float qT[64 * 64];
    __shared__ float ks[64][64];
    __shared__ float vs[64][64];

    int b   = blockIdx.x;
    int w   = b & 255;
    int wwi = w & 15, whi = (w >> 4) & 15;
    bool left = (wwi == 0), top = (whi == 0);

    const float* qb = g_qw + (size_t)b * 4096;
    const float* kb = g_kw + (size_t)b * 4096;
    const float* vb = g_vw + (size_t)b * 4096;
    int tid = threadIdx.x;

    for (int i = tid; i < 1024; i += 64) {
        int r = i >> 4, c = (i & 15) << 2;
        float4 kv = *(const float4*)(kb + (i << 2));
        *(float4*)&ks[r][c] = kv;
        float4 vv = *(const float4*)(vb + (i << 2));
        *(float4*)&vs[r][c] = vv;
        float4 qv = *(const float4*)(qb + (i << 2));
        QT(c + 0, r) = qv.x; QT(c + 1, r) = qv.y;
        QT(c + 2, r) = qv.z; QT(c + 3, r) = qv.w;
    }
    __syncthreads();

    float sarr[64];
    #pragma unroll
    for (int k = 0; k < 64; k++) sarr[k] = 0.f;
    for (int e = 0; e < 64; e += 4) {
        float q0 = QT(e + 0, tid), q1 = QT(e + 1, tid);
        float q2 = QT(e + 2, tid), q3 = QT(e + 3, tid);
        #pragma unroll
        for (int k = 0; k < 64; k++) {
            float4 kv = *(const float4*)&ks[k][e];
            sarr[k] += q0 * kv.x + q1 * kv.y + q2 * kv.z + q3 * kv.w;
        }
    }

    int qh = tid >> 3, qw_ = tid & 7;
    bool qa = qh < SHIFT, ql = qw_ < SHIFT;
    float mx = -3.402823466e38f;
    #pragma unroll
    for (int k = 0; k < 64; k++) {
        int kh = k >> 3, kw = k & 7;
        bool ka = kh < SHIFT, kl = kw < SHIFT;
        bool m = (!left && !top)
               || (left && top && (ql == kl) && (qa == ka))
               || (left && !top && (ql == kl))
               || (!left && top && (qa == ka));
        if (!m) sarr[k] = -3.402823466e38f;
        mx = fmaxf(mx, sarr[k]);
    }
    float sum = 0.f;
    #pragma unroll
    for (int k = 0; k < 64; k++) {
        float p = __expf(sarr[k] - mx);
        sarr[k] = p;
        sum += p;
    }
    float inv = 1.0f / sum;

    float* ob = g_ow + (size_t)b * 4096 + (size_t)tid * 64;
    for (int e = 0; e < 64; e += 4) {
        float ax = 0.f, ay = 0.f, az = 0.f, aw = 0.f;
        #pragma unroll
        for (int k = 0; k < 64; k++) {
            float4 vv = *(const float4*)&vs[k][e];
            float p = sarr[k];
            ax += p * vv.x; ay += p * vv.y; az += p * vv.z; aw += p * vv.w;
        }
        float4 o4 = make_float4(ax * inv, ay * inv, az * inv, aw * inv);
        *(float4*)(ob + e) = o4;
    }
}

// ---------------------------------------------------------------------------
// K5: unwindow -> bf16 hi/lo
// ---------------------------------------------------------------------------
__global__ __launch_bounds__(256) void unwindow_kernel()
{
    int t = blockIdx.x;
    int n = t >> 14;
    int y = (t >> 7) & 127;
    int x = t & 127;
    int Y = (y + SHIFT) & 127, X = (x + SHIFT) & 127;
    int winbase = (Y >> 3) * 16 + (X >> 3);
    int spos = (Y & 7) * 8 + (X & 7);
    #pragma unroll
    for (int i = 0; i < 3; i++) {
        int c = threadIdx.x + 256 * i;
        int h = c >> 6, e = c & 63;
        size_t src = ((size_t)((n * NHEADS + h) * 256 + winbase)) * 4096
                   + (size_t)spos * 64 + e;
        split2(g_ow[src], &g_oi_hi[(size_t)t * DM + c], &g_oi_lo[(size_t)t * DM + c]);
    }
}

// ---------------------------------------------------------------------------
// host
// ---------------------------------------------------------------------------
static void launch_hgemm(const __nv_bfloat16* Ah, const __nv_bfloat16* Al,
                         const __nv_bfloat16* Bh, const __nv_bfloat16* Bl,
                         const float* D, float* C, int M, int N, int K,
                         int ldc, int mode)
{
    dim3 grid(N / 128, M / 128);
    hgemm_kernel<<<grid, 256, GEMM_SMEM>>>(Ah, Al, Bh, Bl, D, C, M, N, K, ldc, mode);
}

extern "C" void kernel_launch(void* const* d_in, const int* in_sizes, int n_in,
                              void* d_out, int out_size)
{
    const float* x          = (const float*)d_in[0];
    const float* pos        = (const float*)d_in[1];
    const float* cond       = (const float*)d_in[2];
    const float* ada1_w     = (const float*)d_in[3];
    const float* qkv_w      = (const float*)d_in[4];
    const float* attn_scale = (const float*)d_in[5];
    const float* rope_freqs = (const float*)d_in[6];
    const float* out_w      = (const float*)d_in[7];
    const float* ada2_w     = (const float*)d_in[8];
    const float* ff_up_w    = (const float*)d_in[9];
    const float* ff_down_w  = (const float*)d_in[10];
    float* out = (float*)d_out;

    cudaFuncSetAttribute(hgemm_kernel, cudaFuncAttributeMaxDynamicSharedMemorySize, GEMM_SMEM);

    float *p_scale1, *p_scale2, *p_qkv, *p_x2;
    __nv_bfloat16 *p_hh, *p_hl, *p_oih, *p_oil, *p_ah, *p_al, *p_wh, *p_wl;
    cudaGetSymbolAddress((void**)&p_scale1, g_scale1);
    cudaGetSymbolAddress((void**)&p_scale2, g_scale2);
    cudaGetSymbolAddress((void**)&p_qkv,    g_qkv);
    cudaGetSymbolAddress((void**)&p_x2,     g_x2);
    cudaGetSymbolAddress((void**)&p_hh,     g_h_hi);
    cudaGetSymbolAddress((void**)&p_hl,     g_h_lo);
    cudaGetSymbolAddress((void**)&p_oih,    g_oi_hi);
    cudaGetSymbolAddress((void**)&p_oil,    g_oi_lo);
    cudaGetSymbolAddress((void**)&p_ah,     g_a_hi);
    cudaGetSymbolAddress((void**)&p_al,     g_a_lo);
    cudaGetSymbolAddress((void**)&p_wh,     g_w_hi);
    cudaGetSymbolAddress((void**)&p_wl,     g_w_lo);

    const int OQKV = 0;
    const int OOUT = OQKV + W_QKV_SZ;
    const int OUP  = OOUT + W_OUT_SZ;
    const int ODN  = OUP + W_UP_SZ;

    wsplit_kernel<<<(W_QKV_SZ + 255) / 256, 256>>>(qkv_w,     p_wh + OQKV, p_wl + OQKV, W_QKV_SZ, DM, 0);
    wsplit_kernel<<<(W_OUT_SZ + 255) / 256, 256>>>(out_w,     p_wh + OOUT, p_wl + OOUT, W_OUT_SZ, DM, 0);
    wsplit_kernel<<<(W_UP_SZ  + 255) / 256, 256>>>(ff_up_w,   p_wh + OUP,  p_wl + OUP,  W_UP_SZ,  DM, 1);
    wsplit_kernel<<<(W_DN_SZ  + 255) / 256, 256>>>(ff_down_w, p_wh + ODN,  p_wl + ODN,  W_DN_SZ,  DFF, 0);

    ada_kernel<<<768, 256>>>(cond, ada1_w, ada2_w);
    rmsnorm_kernel<<<TOKENS, 256>>>(x, p_scale1);
    // qkv: q,k -> g_qkv (ldc=1536); v -> scatter to g_vw
    launch_hgemm(p_hh, p_hl, p_wh + OQKV, p_wl + OQKV, nullptr, p_qkv,
                 TOKENS, 3 * DM, DM, 2 * DM, 2);
    qk_transform_kernel<<<TOKENS, 384>>>(pos, attn_scale, rope_freqs);
    attn_kernel<<<NWIN, 64>>>();
    unwindow_kernel<<<TOKENS, 256>>>();
    launch_hgemm(p_oih, p_oil, p_wh + OOUT, p_wl + OOUT, x, p_x2,
                 TOKENS, DM, DM, DM, 0);
    rmsnorm_kernel<<<TOKENS, 256>>>(p_x2, p_scale2);
    // ff_up with fused gated GELU (interleaved weights) -> g_a_hi/lo
    launch_hgemm(p_hh, p_hl, p_wh + OUP, p_wl + OUP, nullptr, nullptr,
                 TOKENS, 2 * DFF, DM, 2 * DFF, 1);
    launch_hgemm(p_ah, p_al, p_wh + ODN, p_wl + ODN, p_x2, out,
                 TOKENS, DM, DFF, DM, 0);
}